// round 2
// baseline (speedup 1.0000x reference)
#include <cuda_runtime.h>

#define NB  500000
#define OBS 128
#define HD  64
#define AD  16
#define TPB 256
#define GRID ((NB + TPB - 1) / TPB)

// shared: w1[64][128] + wih[192][64] + whh[192][64] + fc2T[64][16] + biases
#define SMEM_FLOATS (8192 + 12288 + 12288 + 1024 + 64 + 192 + 192 + 16)
#define SMEM_BYTES  (SMEM_FLOATS * 4)

// Scratch in case the harness only wants logits in d_out (new_hidden still must
// be computed; it feeds the logits).
__device__ float g_nh_scratch[(size_t)NB * HD];

__device__ __forceinline__ float fast_sigmoid(float v) {
    return __fdividef(1.0f, 1.0f + __expf(-v));
}
__device__ __forceinline__ float fast_tanh(float v) {
    // tanh(x) = 1 - 2/(e^{2x}+1); exact at both saturations, ~1e-7 rel err.
    return 1.0f - __fdividef(2.0f, __expf(2.0f * v) + 1.0f);
}

__global__ void __launch_bounds__(TPB, 1)
gru_actor_kernel(const float* __restrict__ x,
                 const float* __restrict__ h_in,
                 const int*   __restrict__ mask,
                 const float* __restrict__ fc1_w,
                 const float* __restrict__ fc1_b,
                 const float* __restrict__ w_ih,
                 const float* __restrict__ w_hh,
                 const float* __restrict__ b_ih,
                 const float* __restrict__ b_hh,
                 const float* __restrict__ fc2_w,
                 const float* __restrict__ fc2_b,
                 float* __restrict__ out_logits,
                 float* __restrict__ out_h)
{
    extern __shared__ float smem[];
    float* s_w1   = smem;                  // [64][128]  row-major (j,k)
    float* s_wih  = s_w1   + 8192;         // [192][64]
    float* s_whh  = s_wih  + 12288;        // [192][64]
    float* s_fc2t = s_whh  + 12288;        // [64][16]   transposed (j,o)
    float* s_b1   = s_fc2t + 1024;
    float* s_bih  = s_b1   + 64;
    float* s_bhh  = s_bih  + 192;
    float* s_b2   = s_bhh  + 192;

    // ---- stage weights (coalesced, vectorized) ----
    {
        float4*       d1 = (float4*)s_w1;  const float4* g1 = (const float4*)fc1_w;
        for (int i = threadIdx.x; i < 2048; i += TPB) d1[i] = g1[i];
        float4*       d2 = (float4*)s_wih; const float4* g2 = (const float4*)w_ih;
        for (int i = threadIdx.x; i < 3072; i += TPB) d2[i] = g2[i];
        float4*       d3 = (float4*)s_whh; const float4* g3 = (const float4*)w_hh;
        for (int i = threadIdx.x; i < 3072; i += TPB) d3[i] = g3[i];
        for (int i = threadIdx.x; i < 1024; i += TPB) {
            int o = i >> 6, j = i & 63;
            s_fc2t[j * AD + o] = fc2_w[i];
        }
        for (int i = threadIdx.x; i < 64;  i += TPB) s_b1[i] = fc1_b[i];
        for (int i = threadIdx.x; i < 192; i += TPB) { s_bih[i] = b_ih[i]; s_bhh[i] = b_hh[i]; }
        for (int i = threadIdx.x; i < 16;  i += TPB) s_b2[i] = fc2_b[i];
    }
    __syncthreads();

    const int row = blockIdx.x * TPB + threadIdx.x;
    if (row >= NB) return;

    if (out_h == nullptr) out_h = g_nh_scratch;

    // ---- fc1 + tanh: a[j] = tanh(sum_k x[k] * w1[j][k] + b1[j]) ----
    float a[HD];
    #pragma unroll
    for (int j = 0; j < HD; j++) a[j] = s_b1[j];

    const float4* xr = (const float4*)(x + (size_t)row * OBS);
    #pragma unroll 2
    for (int k4 = 0; k4 < OBS / 4; k4++) {
        const float4 xv = __ldg(xr + k4);
        #pragma unroll
        for (int j = 0; j < HD; j++) {
            const float4 wv = *(const float4*)(s_w1 + j * OBS + k4 * 4);
            a[j] = fmaf(xv.x, wv.x, a[j]);
            a[j] = fmaf(xv.y, wv.y, a[j]);
            a[j] = fmaf(xv.z, wv.z, a[j]);
            a[j] = fmaf(xv.w, wv.w, a[j]);
        }
    }
    #pragma unroll
    for (int j = 0; j < HD; j++) a[j] = fast_tanh(a[j]);

    // ---- load hidden state into registers ----
    float h[HD];
    const float4* hr = (const float4*)(h_in + (size_t)row * HD);
    #pragma unroll
    for (int k4 = 0; k4 < HD / 4; k4++) {
        const float4 hv = __ldg(hr + k4);
        h[k4*4+0] = hv.x; h[k4*4+1] = hv.y; h[k4*4+2] = hv.z; h[k4*4+3] = hv.w;
    }

    const bool active = (mask[row] != 0);

    float logit[AD];
    #pragma unroll
    for (int o = 0; o < AD; o++) logit[o] = s_b2[o];

    float4* nh4 = (float4*)(out_h + (size_t)row * HD);

    // ---- GRU gates + masked update + fused fc2 ----
    #pragma unroll 1
    for (int jb = 0; jb < HD / 4; jb++) {
        float nv[4];
        #pragma unroll
        for (int u = 0; u < 4; u++) {
            const int j = jb * 4 + u;
            float ir  = s_bih[j],        hrr = s_bhh[j];
            float iz  = s_bih[HD + j],   hz  = s_bhh[HD + j];
            float in_ = s_bih[2*HD + j], hn  = s_bhh[2*HD + j];
            const float* wr_i = s_wih + j * HD;
            const float* wz_i = s_wih + (HD   + j) * HD;
            const float* wn_i = s_wih + (2*HD + j) * HD;
            const float* wr_h = s_whh + j * HD;
            const float* wz_h = s_whh + (HD   + j) * HD;
            const float* wn_h = s_whh + (2*HD + j) * HD;
            #pragma unroll
            for (int k4 = 0; k4 < HD / 4; k4++) {
                const int k = k4 * 4;
                float4 w0 = *(const float4*)(wr_i + k);
                ir  = fmaf(a[k], w0.x, ir);  ir  = fmaf(a[k+1], w0.y, ir);
                ir  = fmaf(a[k+2], w0.z, ir); ir  = fmaf(a[k+3], w0.w, ir);
                float4 w1v = *(const float4*)(wz_i + k);
                iz  = fmaf(a[k], w1v.x, iz);  iz  = fmaf(a[k+1], w1v.y, iz);
                iz  = fmaf(a[k+2], w1v.z, iz); iz  = fmaf(a[k+3], w1v.w, iz);
                float4 w2 = *(const float4*)(wn_i + k);
                in_ = fmaf(a[k], w2.x, in_);  in_ = fmaf(a[k+1], w2.y, in_);
                in_ = fmaf(a[k+2], w2.z, in_); in_ = fmaf(a[k+3], w2.w, in_);
                float4 w3 = *(const float4*)(wr_h + k);
                hrr = fmaf(h[k], w3.x, hrr);  hrr = fmaf(h[k+1], w3.y, hrr);
                hrr = fmaf(h[k+2], w3.z, hrr); hrr = fmaf(h[k+3], w3.w, hrr);
                float4 w4 = *(const float4*)(wz_h + k);
                hz  = fmaf(h[k], w4.x, hz);   hz  = fmaf(h[k+1], w4.y, hz);
                hz  = fmaf(h[k+2], w4.z, hz); hz  = fmaf(h[k+3], w4.w, hz);
                float4 w5 = *(const float4*)(wn_h + k);
                hn  = fmaf(h[k], w5.x, hn);   hn  = fmaf(h[k+1], w5.y, hn);
                hn  = fmaf(h[k+2], w5.z, hn); hn  = fmaf(h[k+3], w5.w, hn);
            }
            const float r = fast_sigmoid(ir + hrr);
            const float z = fast_sigmoid(iz + hz);
            const float n = fast_tanh(in_ + r * hn);
            // h[j] has dynamic index jb -> reload scalar from global (L1-hot line)
            const float hj  = h_in[(size_t)row * HD + j];
            const float hu  = fmaf(z, hj - n, n);   // (1-z)*n + z*h
            const float nhj = active ? hu : hj;
            nv[u] = nhj;
            #pragma unroll
            for (int o4 = 0; o4 < AD / 4; o4++) {
                const float4 wv = *(const float4*)(s_fc2t + j * AD + o4 * 4);
                logit[o4*4+0] = fmaf(wv.x, nhj, logit[o4*4+0]);
                logit[o4*4+1] = fmaf(wv.y, nhj, logit[o4*4+1]);
                logit[o4*4+2] = fmaf(wv.z, nhj, logit[o4*4+2]);
                logit[o4*4+3] = fmaf(wv.w, nhj, logit[o4*4+3]);
            }
        }
        nh4[jb] = make_float4(nv[0], nv[1], nv[2], nv[3]);
    }

    float4* lg4 = (float4*)(out_logits + (size_t)row * AD);
    #pragma unroll
    for (int q = 0; q < AD / 4; q++)
        lg4[q] = make_float4(logit[q*4+0], logit[q*4+1], logit[q*4+2], logit[q*4+3]);
}

extern "C" void kernel_launch(void* const* d_in, const int* in_sizes, int n_in,
                              void* d_out, int out_size)
{
    const float* x    = (const float*)d_in[0];
    const float* hs   = (const float*)d_in[1];
    const int*   am   = (const int*)d_in[2];
    const float* fc1w = (const float*)d_in[3];
    const float* fc1b = (const float*)d_in[4];
    const float* wih  = (const float*)d_in[5];
    const float* whh  = (const float*)d_in[6];
    const float* bih  = (const float*)d_in[7];
    const float* bhh  = (const float*)d_in[8];
    const float* fc2w = (const float*)d_in[9];
    const float* fc2b = (const float*)d_in[10];

    float* out_logits = (float*)d_out;
    // Expected layout: [logits (B*16) | new_hidden (B*64)]. If the harness only
    // sized d_out for logits, divert new_hidden to device scratch (kernel-side).
    float* out_h = nullptr;
    if ((long long)out_size >= (long long)NB * (AD + HD))
        out_h = out_logits + (size_t)NB * AD;

    cudaFuncSetAttribute(gru_actor_kernel,
                         cudaFuncAttributeMaxDynamicSharedMemorySize, SMEM_BYTES);

    gru_actor_kernel<<<GRID, TPB, SMEM_BYTES>>>(
        x, hs, am, fc1w, fc1b, wih, whh, bih, bhh, fc2w, fc2b,
        out_logits, out_h);
}

// round 7
// speedup vs baseline: 3.8526x; 3.8526x over previous
#include <cuda_runtime.h>
#include <cuda_bf16.h>
#include <cstdint>

#define NB    500000
#define OBS   128
#define HD    64
#define AD    16
#define TPB   256
#define GRID  148
#define NBLK  (NB / 16)          // 31250 16-row blocks, exact

// ---- SMEM layout (bytes) ----
// biases f32, then weight matrices as bf16 hi/lo in ldmatrix-friendly padded rows
#define OFF_B1    0               // 64 f32
#define OFF_BIH   256             // 192 f32
#define OFF_BHH   1024            // 192 f32
#define OFF_B2    1792            // 16 f32
#define RS1       272             // w1 row stride bytes (128 bf16 + 8 pad)
#define RSG       144             // 64-K matrices row stride bytes (64 bf16 + 8 pad)
#define OFF_W1HI  1856
#define OFF_W1LO  (OFF_W1HI + 64*RS1)        // 19264
#define OFF_IHHI  (OFF_W1LO + 64*RS1)        // 36672
#define OFF_IHLO  (OFF_IHHI + 192*RSG)       // 64320
#define OFF_HHHI  (OFF_IHLO + 192*RSG)       // 91968
#define OFF_HHLO  (OFF_HHHI + 192*RSG)       // 119616
#define OFF_F2HI  (OFF_HHLO + 192*RSG)       // 147264
#define OFF_F2LO  (OFF_F2HI + 16*RSG)        // 149568
#define SMEM_BYTES (OFF_F2LO + 16*RSG)       // 151872

__device__ float g_nh_scratch[(size_t)NB * HD];

__device__ __forceinline__ float fast_sigmoid(float v) { return __fdividef(1.0f, 1.0f + __expf(-v)); }
__device__ __forceinline__ float fast_tanh(float v)    { return 1.0f - __fdividef(2.0f, __expf(2.0f * v) + 1.0f); }

__device__ __forceinline__ uint32_t smem_u32(const void* p) {
    uint32_t a;
    asm("{ .reg .u64 t; cvta.to.shared.u64 t, %1; cvt.u32.u64 %0, t; }" : "=r"(a) : "l"(p));
    return a;
}

// hi/lo bf16 split of a float pair, packed for mma (low half = first element)
__device__ __forceinline__ uint32_t packsplit(float x, float y, uint32_t& lo) {
    __nv_bfloat162 h = __floats2bfloat162_rn(x, y);
    float rx = x - __bfloat162float(h.x);
    float ry = y - __bfloat162float(h.y);
    __nv_bfloat162 l = __floats2bfloat162_rn(rx, ry);
    lo = *reinterpret_cast<uint32_t*>(&l);
    return *reinterpret_cast<uint32_t*>(&h);
}

// D = A(16x16 bf16) * B(16x8 bf16) + D, fp32 accum
__device__ __forceinline__ void mma16816(float d[4], const uint32_t a[4], uint32_t b0, uint32_t b1) {
    asm volatile("mma.sync.aligned.m16n8k16.row.col.f32.bf16.bf16.f32 "
                 "{%0,%1,%2,%3}, {%4,%5,%6,%7}, {%8,%9}, {%0,%1,%2,%3};"
                 : "+f"(d[0]), "+f"(d[1]), "+f"(d[2]), "+f"(d[3])
                 : "r"(a[0]), "r"(a[1]), "r"(a[2]), "r"(a[3]), "r"(b0), "r"(b1));
}

// ldmatrix x4: 4 8x8 b16 tiles; we arrange addresses so regs = B frags for k0-15, k16-31
__device__ __forceinline__ void ldB4(uint32_t addr, uint32_t b[4]) {
    asm volatile("ldmatrix.sync.aligned.m8n8.x4.shared.b16 {%0,%1,%2,%3}, [%4];"
                 : "=r"(b[0]), "=r"(b[1]), "=r"(b[2]), "=r"(b[3]) : "r"(addr));
}

// one k32 block with 3-way hi/lo split (drops only lo*lo): 6 HMMA
__device__ __forceinline__ void mma_k32(float d[4],
        const uint32_t AhA[4], const uint32_t AhB[4],
        const uint32_t AlA[4], const uint32_t AlB[4],
        const uint32_t Bh[4],  const uint32_t Bl[4]) {
    mma16816(d, AhA, Bh[0], Bh[1]);
    mma16816(d, AhB, Bh[2], Bh[3]);
    mma16816(d, AlA, Bh[0], Bh[1]);
    mma16816(d, AlB, Bh[2], Bh[3]);
    mma16816(d, AhA, Bl[0], Bl[1]);
    mma16816(d, AhB, Bl[2], Bl[3]);
}

// load a 16x16 A-fragment (hi/lo) straight from global f32 (row r.., col c..)
__device__ __forceinline__ void ldA_g(const float* __restrict__ g, int S, int r, int c,
                                      uint32_t hi[4], uint32_t lo[4]) {
    float2 v;
    v = *(const float2*)(g + (size_t)r       * S + c);     hi[0] = packsplit(v.x, v.y, lo[0]);
    v = *(const float2*)(g + (size_t)(r + 8) * S + c);     hi[1] = packsplit(v.x, v.y, lo[1]);
    v = *(const float2*)(g + (size_t)r       * S + c + 8); hi[2] = packsplit(v.x, v.y, lo[2]);
    v = *(const float2*)(g + (size_t)(r + 8) * S + c + 8); hi[3] = packsplit(v.x, v.y, lo[3]);
}

// i- and h-side MMAs of one gate (N=64, K=64)
__device__ __forceinline__ void gate_mma(uint32_t bIHhi, uint32_t bIHlo,
                                         uint32_t bHHhi, uint32_t bHHlo,
                                         const uint32_t (&Aah)[4][4], const uint32_t (&Aal)[4][4],
                                         const uint32_t (&Ahh)[4][4], const uint32_t (&Ahl)[4][4],
                                         float (&Di)[8][4], float (&Dh)[8][4]) {
    #pragma unroll
    for (int n = 0; n < 8; n++)
        #pragma unroll
        for (int i = 0; i < 4; i++) { Di[n][i] = 0.f; Dh[n][i] = 0.f; }
    #pragma unroll
    for (int kk = 0; kk < 2; kk++) {
        #pragma unroll
        for (int n = 0; n < 8; n++) {
            uint32_t Bh[4], Bl[4];
            ldB4(bIHhi + n * (8 * RSG) + kk * 64, Bh);
            ldB4(bIHlo + n * (8 * RSG) + kk * 64, Bl);
            mma_k32(Di[n], Aah[2*kk], Aah[2*kk+1], Aal[2*kk], Aal[2*kk+1], Bh, Bl);
            ldB4(bHHhi + n * (8 * RSG) + kk * 64, Bh);
            ldB4(bHHlo + n * (8 * RSG) + kk * 64, Bl);
            mma_k32(Dh[n], Ahh[2*kk], Ahh[2*kk+1], Ahl[2*kk], Ahl[2*kk+1], Bh, Bl);
        }
    }
}

__global__ void __launch_bounds__(TPB, 1)
gru_hmma_kernel(const float* __restrict__ x,   const float* __restrict__ h_in,
                const int*   __restrict__ mask,
                const float* __restrict__ fc1_w, const float* __restrict__ fc1_b,
                const float* __restrict__ w_ih,  const float* __restrict__ w_hh,
                const float* __restrict__ b_ih,  const float* __restrict__ b_hh,
                const float* __restrict__ fc2_w, const float* __restrict__ fc2_b,
                float* __restrict__ out_logits,  float* __restrict__ out_h)
{
    extern __shared__ char smem[];
    const int tid  = threadIdx.x;
    const int lane = tid & 31;
    const int wid  = tid >> 5;

    float* s_b1  = (float*)(smem + OFF_B1);
    float* s_bih = (float*)(smem + OFF_BIH);
    float* s_bhh = (float*)(smem + OFF_BHH);
    float* s_b2  = (float*)(smem + OFF_B2);

    if (out_h == nullptr) out_h = g_nh_scratch;

    // ---- stage weights once: f32 -> bf16 hi/lo, padded rows ----
    {
        for (int i = tid; i < 64 * 128; i += TPB) {          // fc1_w [64][128]
            int r = i >> 7, k = i & 127;
            float f = fc1_w[i];
            __nv_bfloat16 hv = __float2bfloat16_rn(f);
            __nv_bfloat16 lv = __float2bfloat16_rn(f - __bfloat162float(hv));
            *(__nv_bfloat16*)(smem + OFF_W1HI + r * RS1 + 2 * k) = hv;
            *(__nv_bfloat16*)(smem + OFF_W1LO + r * RS1 + 2 * k) = lv;
        }
        for (int i = tid; i < 192 * 64; i += TPB) {          // w_ih / w_hh [192][64]
            int r = i >> 6, k = i & 63;
            float f = w_ih[i];
            __nv_bfloat16 hv = __float2bfloat16_rn(f);
            *(__nv_bfloat16*)(smem + OFF_IHHI + r * RSG + 2 * k) = hv;
            *(__nv_bfloat16*)(smem + OFF_IHLO + r * RSG + 2 * k) =
                __float2bfloat16_rn(f - __bfloat162float(hv));
            f = w_hh[i];
            hv = __float2bfloat16_rn(f);
            *(__nv_bfloat16*)(smem + OFF_HHHI + r * RSG + 2 * k) = hv;
            *(__nv_bfloat16*)(smem + OFF_HHLO + r * RSG + 2 * k) =
                __float2bfloat16_rn(f - __bfloat162float(hv));
        }
        for (int i = tid; i < 16 * 64; i += TPB) {           // fc2_w [16][64]
            int r = i >> 6, k = i & 63;
            float f = fc2_w[i];
            __nv_bfloat16 hv = __float2bfloat16_rn(f);
            *(__nv_bfloat16*)(smem + OFF_F2HI + r * RSG + 2 * k) = hv;
            *(__nv_bfloat16*)(smem + OFF_F2LO + r * RSG + 2 * k) =
                __float2bfloat16_rn(f - __bfloat162float(hv));
        }
        for (int i = tid; i < 64;  i += TPB) s_b1[i] = fc1_b[i];
        for (int i = tid; i < 192; i += TPB) { s_bih[i] = b_ih[i]; s_bhh[i] = b_hh[i]; }
        for (int i = tid; i < 16;  i += TPB) s_b2[i] = fc2_b[i];
    }
    __syncthreads();

    const uint32_t sbase = smem_u32(smem);
    // lane-adjusted ldmatrix base addresses (lane&7 supplies the matrix row, lane>>3 the k-chunk)
    const uint32_t lA1 = (lane & 7) * RS1 + (lane >> 3) * 16;
    const uint32_t lAG = (lane & 7) * RSG + (lane >> 3) * 16;
    const uint32_t bW1h = sbase + OFF_W1HI + lA1, bW1l = sbase + OFF_W1LO + lA1;
    const uint32_t bIHh = sbase + OFF_IHHI + lAG, bIHl = sbase + OFF_IHLO + lAG;
    const uint32_t bHHh = sbase + OFF_HHHI + lAG, bHHl = sbase + OFF_HHLO + lAG;
    const uint32_t bF2h = sbase + OFF_F2HI + lAG, bF2l = sbase + OFF_F2LO + lAG;

    const int cb = 2 * (lane & 3);            // fragment column base for this lane
    const int gwid  = blockIdx.x * 8 + wid;   // global warp id (independent worker)
    const int nwork = GRID * 8;

    for (int blk = gwid; blk < NBLK; blk += nwork) {
        const int m0 = blk * 16;
        const int gr = m0 + (lane >> 2);      // this lane's base global row

        // ================= fc1: D = x @ w1^T  (M16, N64, K128) =================
        float D[8][4];
        #pragma unroll
        for (int n = 0; n < 8; n++)
            #pragma unroll
            for (int i = 0; i < 4; i++) D[n][i] = 0.f;

        #pragma unroll
        for (int kk = 0; kk < 4; kk++) {
            uint32_t AhA[4], AlA[4], AhB[4], AlB[4];
            ldA_g(x, OBS, gr, kk * 32 + cb,      AhA, AlA);
            ldA_g(x, OBS, gr, kk * 32 + 16 + cb, AhB, AlB);
            #pragma unroll
            for (int n = 0; n < 8; n++) {
                uint32_t Bh[4], Bl[4];
                ldB4(bW1h + n * (8 * RS1) + kk * 64, Bh);
                ldB4(bW1l + n * (8 * RS1) + kk * 64, Bl);
                mma_k32(D[n], AhA, AhB, AlA, AlB, Bh, Bl);
            }
        }

        // a = tanh(D + b1), converted in-register to gate A-fragments (hi/lo)
        uint32_t Aah[4][4], Aal[4][4];
        #pragma unroll
        for (int n = 0; n < 8; n++)
            #pragma unroll
            for (int i = 0; i < 4; i++)
                D[n][i] = fast_tanh(D[n][i] + s_b1[8 * n + cb + (i & 1)]);
        #pragma unroll
        for (int c = 0; c < 4; c++) {
            Aah[c][0] = packsplit(D[2*c][0],   D[2*c][1],   Aal[c][0]);
            Aah[c][1] = packsplit(D[2*c][2],   D[2*c][3],   Aal[c][1]);
            Aah[c][2] = packsplit(D[2*c+1][0], D[2*c+1][1], Aal[c][2]);
            Aah[c][3] = packsplit(D[2*c+1][2], D[2*c+1][3], Aal[c][3]);
        }

        // h A-fragments straight from global
        uint32_t Ahh[4][4], Ahl[4][4];
        #pragma unroll
        for (int c = 0; c < 4; c++)
            ldA_g(h_in, HD, gr, c * 16 + cb, Ahh[c], Ahl[c]);

        const int mA = mask[gr];
        const int mB = mask[gr + 8];

        float Di[8][4], Dh[8][4], rv[8][4];

        // ---- gate r (rows 0..63) ----
        gate_mma(bIHh, bIHl, bHHh, bHHl, Aah, Aal, Ahh, Ahl, Di, Dh);
        #pragma unroll
        for (int n = 0; n < 8; n++)
            #pragma unroll
            for (int i = 0; i < 4; i++) {
                const int col = 8 * n + cb + (i & 1);
                rv[n][i] = fast_sigmoid(Di[n][i] + Dh[n][i] + s_bih[col] + s_bhh[col]);
            }

        // ---- gate n (rows 128..191): nv = tanh(i_n + b + r*(h_n + b)) ----
        gate_mma(bIHh + 128 * RSG, bIHl + 128 * RSG, bHHh + 128 * RSG, bHHl + 128 * RSG,
                 Aah, Aal, Ahh, Ahl, Di, Dh);
        #pragma unroll
        for (int n = 0; n < 8; n++)
            #pragma unroll
            for (int i = 0; i < 4; i++) {
                const int col = 8 * n + cb + (i & 1);
                rv[n][i] = fast_tanh(Di[n][i] + s_bih[128 + col] +
                                     rv[n][i] * (Dh[n][i] + s_bhh[128 + col]));
            }

        // ---- gate z (rows 64..127) + update + mask ----
        gate_mma(bIHh + 64 * RSG, bIHl + 64 * RSG, bHHh + 64 * RSG, bHHl + 64 * RSG,
                 Aah, Aal, Ahh, Ahl, Di, Dh);
        float nh[8][4];
        #pragma unroll
        for (int n = 0; n < 8; n++) {
            #pragma unroll
            for (int i = 0; i < 4; i++) {
                const int col = 8 * n + cb + (i & 1);
                const float zv = fast_sigmoid(Di[n][i] + Dh[n][i] + s_bih[64 + col] + s_bhh[64 + col]);
                // recompose h_old from the hi/lo A-fragments (D(n,i) <-> chunk n/2, reg (n&1)*2+(i>>1), half i&1)
                const int c = n >> 1, ri = ((n & 1) << 1) + (i >> 1);
                __nv_bfloat162 hh = *reinterpret_cast<__nv_bfloat162*>(&Ahh[c][ri]);
                __nv_bfloat162 hl = *reinterpret_cast<__nv_bfloat162*>(&Ahl[c][ri]);
                const float hold = (i & 1) ? (__bfloat162float(hh.y) + __bfloat162float(hl.y))
                                           : (__bfloat162float(hh.x) + __bfloat162float(hl.x));
                const float hu = fmaf(zv, hold - rv[n][i], rv[n][i]);
                nh[n][i] = ((i < 2) ? mA : mB) ? hu : hold;
            }
            // store new hidden (8B per lane, fully covered lines)
            *(float2*)(out_h + (size_t)gr       * HD + 8 * n + cb) = make_float2(nh[n][0], nh[n][1]);
            *(float2*)(out_h + (size_t)(gr + 8) * HD + 8 * n + cb) = make_float2(nh[n][2], nh[n][3]);
        }

        // ================= fc2: logits = nh @ fc2^T (N16, K64) =================
        #pragma unroll
        for (int c = 0; c < 4; c++) {                 // nh -> A frags (reuse Aa regs)
            Aah[c][0] = packsplit(nh[2*c][0],   nh[2*c][1],   Aal[c][0]);
            Aah[c][1] = packsplit(nh[2*c][2],   nh[2*c][3],   Aal[c][1]);
            Aah[c][2] = packsplit(nh[2*c+1][0], nh[2*c+1][1], Aal[c][2]);
            Aah[c][3] = packsplit(nh[2*c+1][2], nh[2*c+1][3], Aal[c][3]);
        }
        float Dl[2][4];
        #pragma unroll
        for (int nt = 0; nt < 2; nt++)
            #pragma unroll
            for (int i = 0; i < 4; i++) Dl[nt][i] = 0.f;
        #pragma unroll
        for (int kk = 0; kk < 2; kk++)
            #pragma unroll
            for (int nt = 0; nt < 2; nt++) {
                uint32_t Bh[4], Bl[4];
                ldB4(bF2h + nt * (8 * RSG) + kk * 64, Bh);
                ldB4(bF2l + nt * (8 * RSG) + kk * 64, Bl);
                mma_k32(Dl[nt], Aah[2*kk], Aah[2*kk+1], Aal[2*kk], Aal[2*kk+1], Bh, Bl);
            }
        #pragma unroll
        for (int nt = 0; nt < 2; nt++) {
            const int col0 = 8 * nt + cb;
            *(float2*)(out_logits + (size_t)gr       * AD + col0) =
                make_float2(Dl[nt][0] + s_b2[col0], Dl[nt][1] + s_b2[col0 + 1]);
            *(float2*)(out_logits + (size_t)(gr + 8) * AD + col0) =
                make_float2(Dl[nt][2] + s_b2[col0], Dl[nt][3] + s_b2[col0 + 1]);
        }
    }
}

extern "C" void kernel_launch(void* const* d_in, const int* in_sizes, int n_in,
                              void* d_out, int out_size)
{
    const float* x    = (const float*)d_in[0];
    const float* hs   = (const float*)d_in[1];
    const int*   am   = (const int*)d_in[2];
    const float* fc1w = (const float*)d_in[3];
    const float* fc1b = (const float*)d_in[4];
    const float* wih  = (const float*)d_in[5];
    const float* whh  = (const float*)d_in[6];
    const float* bih  = (const float*)d_in[7];
    const float* bhh  = (const float*)d_in[8];
    const float* fc2w = (const float*)d_in[9];
    const float* fc2b = (const float*)d_in[10];

    float* out_logits = (float*)d_out;
    float* out_h = nullptr;
    if ((long long)out_size >= (long long)NB * (AD + HD))
        out_h = out_logits + (size_t)NB * AD;

    cudaFuncSetAttribute(gru_hmma_kernel,
                         cudaFuncAttributeMaxDynamicSharedMemorySize, SMEM_BYTES);

    gru_hmma_kernel<<<GRID, TPB, SMEM_BYTES>>>(
        x, hs, am, fc1w, fc1b, wih, whh, bih, bhh, fc2w, fc2b,
        out_logits, out_h);
}